// round 4
// baseline (speedup 1.0000x reference)
#include <cuda_runtime.h>
#include <cuda_fp16.h>

// Problem constants
constexpr int BB = 256;   // batch
constexpr int KK = 8;     // in_size
constexpr int II = 1152;  // in_node_num
constexpr int NN = 10;    // num_node
constexpr int OO = 16;    // node_size
constexpr int PLANE = BB * OO;                  // 4096 halves per (i,n)
constexpr int UHAT_ELEMS = II * NN * BB * OO;   // 47,185,920
constexpr int ICH_F = 8;                        // i-chunk for fused uv pass

// Static device scratch (allocation-free)
__device__ __half g_uhat[UHAT_ELEMS];           // ~94.4 MB, layout [i][n][b][o]
__device__ float  g_xt[II * BB * KK];           // xt[i][b][k]
__device__ float  g_bij[II * NN];
__device__ float  g_c[II * NN];
__device__ float  g_v[BB * NN * OO];

// packed f32x2 FMA (sm_100+): full fp32 precision, 2x FFMA throughput
#define FMA_F32X2(out, a, b, c) \
    asm("fma.rn.f32x2 %0, %1, %2, %3;" : "=l"(out) : "l"(a), "l"(b), "l"(c))

__device__ __forceinline__ unsigned long long packf2(float lo, float hi) {
    unsigned long long r;
    asm("mov.b64 %0, {%1, %2};" : "=l"(r) : "f"(lo), "f"(hi));
    return r;
}
__device__ __forceinline__ float2 unpackf2(unsigned long long p) {
    float2 r;
    asm("mov.b64 {%0, %1}, %2;" : "=f"(r.x), "=f"(r.y) : "l"(p));
    return r;
}

// ---------------------------------------------------------------------------
// K0: transpose x (B,K,I) viewed as 2048 x 1152  ->  xt 1152 x 2048
__global__ __launch_bounds__(256) void k_transpose(const float* __restrict__ x) {
    __shared__ float tile[32][33];
    int tx = threadIdx.x, ty = threadIdx.y;
    int cbase = blockIdx.x * 32;   // i
    int rbase = blockIdx.y * 32;   // bk
#pragma unroll
    for (int j = 0; j < 32; j += 8)
        tile[ty + j][tx] = x[(size_t)(rbase + ty + j) * II + (cbase + tx)];
    __syncthreads();
#pragma unroll
    for (int j = 0; j < 32; j += 8)
        g_xt[(size_t)(cbase + ty + j) * (BB * KK) + (rbase + tx)] = tile[tx][ty + j];
}

// ---------------------------------------------------------------------------
// K1: build u_hat[i][n][b][o] = sum_k 0.03*W[i,n,o,k] * xt[i][b][k]  (fp16)
// One block per i, thread t == b. Packed f32x2 FMAs, direct coalesced stores.
__global__ __launch_bounds__(256) void k_build(const float* __restrict__ W) {
    int i = blockIdx.x;
    int t = threadIdx.x;                         // = b
    __shared__ unsigned long long sWp[NN * 8 * KK];  // 640 packed pairs (5KB)

    const float* Wi = W + (size_t)i * NN * OO * KK;
    for (int p = t; p < NN * 8 * KK; p += 256) {
        int n = p >> 6, o2 = (p >> 3) & 7, k = p & 7;
        float w0 = 0.03f * Wi[(n * OO + 2 * o2) * KK + k];
        float w1 = 0.03f * Wi[(n * OO + 2 * o2 + 1) * KK + k];
        sWp[p] = packf2(w0, w1);
    }

    // x broadcast pairs {x_k, x_k}
    const float4* xp = reinterpret_cast<const float4*>(g_xt + ((size_t)i * BB + t) * KK);
    float4 xa = xp[0], xc = xp[1];
    unsigned long long xb[8];
    xb[0] = packf2(xa.x, xa.x); xb[1] = packf2(xa.y, xa.y);
    xb[2] = packf2(xa.z, xa.z); xb[3] = packf2(xa.w, xa.w);
    xb[4] = packf2(xc.x, xc.x); xb[5] = packf2(xc.y, xc.y);
    xb[6] = packf2(xc.z, xc.z); xb[7] = packf2(xc.w, xc.w);
    __syncthreads();

    for (int n = 0; n < NN; n++) {
        __half2 oh[8];
#pragma unroll
        for (int o2 = 0; o2 < 8; o2++) {
            unsigned long long acc = 0ull;
            const unsigned long long* wp = &sWp[(n * 8 + o2) * KK];
#pragma unroll
            for (int k = 0; k < KK; k++) FMA_F32X2(acc, wp[k], xb[k], acc);
            float2 d = unpackf2(acc);
            oh[o2] = __floats2half2_rn(d.x, d.y);
        }
        uint4* dst = reinterpret_cast<uint4*>(g_uhat + (((size_t)i * NN + n) * BB + t) * OO);
        dst[0] = *reinterpret_cast<const uint4*>(&oh[0]);
        dst[1] = *reinterpret_cast<const uint4*>(&oh[4]);
    }
}

// ---------------------------------------------------------------------------
// K2: fused s-pass + squash. No partial buffers, no second kernel.
// 2560 (b,n) pairs x 8 o-pairs = 20480 slots == grid 128 x block 160, exact.
// Thread: full i-loop (1152 half2 loads, stride 80KB), fp32 accumulate,
// then 8-lane shfl group computes |s|^2 -> v written to g_v and out.
__global__ __launch_bounds__(160) void k_ss(int use_const, float* __restrict__ out) {
    __shared__ float sc[II * NN];   // 46 KB: all routing coefficients
    int t = threadIdx.x;
    int slot = blockIdx.x * 160 + t;
    int pair = slot >> 3, opair = slot & 7;
    int n = pair % NN, b = pair / NN;

    if (!use_const) {
        for (int j = t; j < II * NN; j += 160) sc[j] = g_c[j];
        __syncthreads();
    }

    const __half2* base = reinterpret_cast<const __half2*>(g_uhat)
                        + (size_t)n * (PLANE / 2) + b * (OO / 2) + opair;
    const size_t stride = (size_t)NN * (PLANE / 2);   // one i step in half2

    float a0 = 0.0f, a1 = 0.0f;
    if (use_const) {
#pragma unroll 16
        for (int i = 0; i < II; i++) {
            float2 f = __half22float2(base[(size_t)i * stride]);
            a0 += f.x; a1 += f.y;
        }
        a0 *= 0.1f; a1 *= 0.1f;
    } else {
#pragma unroll 16
        for (int i = 0; i < II; i++) {
            float2 f = __half22float2(base[(size_t)i * stride]);
            float cc = sc[i * NN + n];
            a0 += cc * f.x; a1 += cc * f.y;
        }
    }

    // squash over the 16 o's = this 8-lane o-group (2 floats per lane)
    float m = a0 * a0 + a1 * a1;
    m += __shfl_xor_sync(0xffffffffu, m, 1);
    m += __shfl_xor_sync(0xffffffffu, m, 2);
    m += __shfl_xor_sync(0xffffffffu, m, 4);
    float mag = sqrtf(m);
    float s2 = mag / (1.0f + m);
    float2 v = make_float2(a0 * s2, a1 * s2);
    int idx = pair * OO + opair * 2;
    *reinterpret_cast<float2*>(&g_v[idx]) = v;
    *reinterpret_cast<float2*>(&out[idx]) = v;
}

// ---------------------------------------------------------------------------
// K3: fused agreement + routing update:
//   uv[i,n] = sum_{b,o} u_hat[i,n,b,o]*v[b,n,o];  b += uv/B;  c = softmax_n(b)
// grid = 144 (i-chunks of 8), block 320 = 10 warps (warp w == n).
// Each lane owns 16 fixed uint4 slots of the 512-uint4 plane (FULL batch).
__global__ __launch_bounds__(320) void k_fused(int first) {
    int i0 = blockIdx.x * ICH_F;
    int w  = threadIdx.x >> 5;     // n
    int l  = threadIdx.x & 31;

    // preload v at this lane's fixed (b,o) slots: 128 registers (full plane)
    float vr[128];
#pragma unroll
    for (int s = 0; s < 16; s++) {
        int j = l + 32 * s;               // uint4 slot 0..511
        int b = j >> 1, o0 = (j & 1) * 8;
        const float4* vp = reinterpret_cast<const float4*>(&g_v[(b * NN + w) * OO + o0]);
        float4 v0 = vp[0], v1 = vp[1];
        vr[s * 8 + 0] = v0.x; vr[s * 8 + 1] = v0.y; vr[s * 8 + 2] = v0.z; vr[s * 8 + 3] = v0.w;
        vr[s * 8 + 4] = v1.x; vr[s * 8 + 5] = v1.y; vr[s * 8 + 6] = v1.z; vr[s * 8 + 7] = v1.w;
    }

    __shared__ float suv[ICH_F][NN];

    for (int q = 0; q < ICH_F; q++) {
        int i = i0 + q;
        const uint4* base = reinterpret_cast<const uint4*>(g_uhat)
                          + (size_t)(i * NN + w) * (PLANE / 8);
        float acc = 0.0f;
#pragma unroll
        for (int g2 = 0; g2 < 2; g2++) {
            uint4 u[8];
#pragma unroll
            for (int s = 0; s < 8; s++) u[s] = base[l + 32 * (g2 * 8 + s)];
#pragma unroll
            for (int s = 0; s < 8; s++) {
                const __half2* h = reinterpret_cast<const __half2*>(&u[s]);
                int vb = (g2 * 8 + s) * 8;
#pragma unroll
                for (int p = 0; p < 4; p++) {
                    float2 f = __half22float2(h[p]);
                    acc += f.x * vr[vb + 2 * p] + f.y * vr[vb + 2 * p + 1];
                }
            }
        }
#pragma unroll
        for (int sft = 16; sft > 0; sft >>= 1)
            acc += __shfl_xor_sync(0xffffffffu, acc, sft);
        if (l == 0) suv[q][w] = acc;
    }
    __syncthreads();

    if (threadIdx.x < ICH_F) {
        int i = i0 + threadIdx.x;
        float bv[NN];
        float m = -1e30f;
#pragma unroll
        for (int n = 0; n < NN; n++) {
            float bprev = first ? 0.0f : g_bij[i * NN + n];
            bv[n] = bprev + suv[threadIdx.x][n] * (1.0f / BB);
            m = fmaxf(m, bv[n]);
        }
        if (first) {
#pragma unroll
            for (int n = 0; n < NN; n++) g_bij[i * NN + n] = bv[n];
        }
        float sum = 0.0f;
#pragma unroll
        for (int n = 0; n < NN; n++) { bv[n] = __expf(bv[n] - m); sum += bv[n]; }
        float inv = 1.0f / sum;
#pragma unroll
        for (int n = 0; n < NN; n++) g_c[i * NN + n] = bv[n] * inv;
    }
}

// ---------------------------------------------------------------------------
extern "C" void kernel_launch(void* const* d_in, const int* in_sizes, int n_in,
                              void* d_out, int out_size) {
    const float* x = (const float*)d_in[0];   // (256, 8, 1152) fp32
    const float* W = (const float*)d_in[1];   // (1, 1152, 10, 16, 8) fp32
    float* out = (float*)d_out;               // (256, 10, 16, 1) fp32

    k_transpose<<<dim3(II / 32, (BB * KK) / 32), dim3(32, 8)>>>(x);
    k_build<<<II, 256>>>(W);

    // iter 1: c is uniform 0.1 (softmax of zeros)
    k_ss<<<128, 160>>>(1, out);
    // iter 2
    k_fused<<<II / ICH_F, 320>>>(1);
    k_ss<<<128, 160>>>(0, out);
    // iter 3
    k_fused<<<II / ICH_F, 320>>>(0);
    k_ss<<<128, 160>>>(0, out);
}

// round 5
// speedup vs baseline: 3.9103x; 3.9103x over previous
#include <cuda_runtime.h>
#include <cuda_fp16.h>
#include <cstdint>

// Problem constants
constexpr int BB = 256;    // batch
constexpr int KK = 8;      // in_size
constexpr int II = 1152;   // in_node_num
constexpr int NN = 10;     // num_node
constexpr int OO = 16;     // node_size
constexpr int IK = II * KK;   // 9216
constexpr int NO = NN * OO;   // 160
constexpr int KC = 36;        // split-K chunks for s-GEMM (9216/256)
constexpr int KCW = IK / KC;  // 256

// Static device scratch (~24 MB total, L2-resident)
__device__ __half g_xh [BB * IK];     // xh[b][i*8+k]      4.7 MB
__device__ __half g_xhT[IK * BB];     // xhT[i*8+k][b]     4.7 MB
__device__ float  g_Wps[II * NO * KK];// Wps[i][n][o][k]   5.9 MB (0.03*W)
__device__ __half g_A  [NO * IK];     // A[n*16+o][i*8+k]  2.95 MB (c * Wps)
__device__ float  g_sp [KC][BB * NO]; // split-K partials  5.9 MB
__device__ __half g_vT [NO * BB];     // vT[no][b]         80 KB
__device__ float  g_bij[II * NN];

// ---------------------------------------------------------------------------
__device__ __forceinline__ void mma16816(float* c, uint32_t a0, uint32_t a1,
                                         uint32_t a2, uint32_t a3,
                                         uint32_t b0, uint32_t b1) {
    asm volatile(
        "mma.sync.aligned.m16n8k16.row.col.f32.f16.f16.f32 "
        "{%0,%1,%2,%3}, {%4,%5,%6,%7}, {%8,%9}, {%0,%1,%2,%3};"
        : "+f"(c[0]), "+f"(c[1]), "+f"(c[2]), "+f"(c[3])
        : "r"(a0), "r"(a1), "r"(a2), "r"(a3), "r"(b0), "r"(b1));
}

__device__ __forceinline__ uint32_t ld_h2(const __half* p) {
    return *reinterpret_cast<const uint32_t*>(p);
}

// ---------------------------------------------------------------------------
// P0: pack x (B,K,I) fp32 -> xh[b][ik] fp16 and xhT[ik][b] fp16
// grid (36, 8): 32 i x 32 b tile, 256 threads
__global__ __launch_bounds__(256) void k_prep_x(const float* __restrict__ x) {
    __shared__ float tf[32][32][9];   // [b][i][k], pad 9
    int t = threadIdx.x;
    int i0 = blockIdx.x * 32, b0 = blockIdx.y * 32;
    int kk = t >> 5, il = t & 31;
#pragma unroll
    for (int j = 0; j < 32; j++)
        tf[j][il][kk] = x[((size_t)(b0 + j) * KK + kk) * II + i0 + il];
    __syncthreads();

    // xh: 32 b rows x 256 halves
#pragma unroll
    for (int jj = 0; jj < 4; jj++) {
        int s = jj * 256 + t;
        int bl = s >> 5, u = s & 31;       // u = i_local
        __half h[8];
#pragma unroll
        for (int k = 0; k < 8; k++) h[k] = __float2half_rn(tf[bl][u][k]);
        *reinterpret_cast<uint4*>(&g_xh[(size_t)(b0 + bl) * IK + (i0 + u) * 8]) =
            *reinterpret_cast<const uint4*>(h);
    }
    // xhT: 256 ik rows x 32 b
#pragma unroll
    for (int jj = 0; jj < 4; jj++) {
        int s = jj * 256 + t;
        int row = s >> 2, w = s & 3;       // row = i_l*8+k, w = b-octet
        int il2 = row >> 3, k = row & 7;
        __half h[8];
#pragma unroll
        for (int bb = 0; bb < 8; bb++) h[bb] = __float2half_rn(tf[w * 8 + bb][il2][k]);
        *reinterpret_cast<uint4*>(&g_xhT[(size_t)((i0 + il2) * 8 + k) * BB + b0 + w * 8]) =
            *reinterpret_cast<const uint4*>(h);
    }
}

// ---------------------------------------------------------------------------
// P1: Wps = 0.03*W ; A0 = 0.1*Wps (iteration-1 routing matrix). grid 720.
__global__ __launch_bounds__(256) void k_prep_w(const float* __restrict__ W) {
    int tid = blockIdx.x * 256 + threadIdx.x;   // (i*160 + no), 0..184319
    if (tid >= II * NO) return;
    int i = tid / NO, no = tid % NO;
    float4 w0 = *reinterpret_cast<const float4*>(&W[(size_t)tid * 8]);
    float4 w1 = *reinterpret_cast<const float4*>(&W[(size_t)tid * 8 + 4]);
    float s = 0.03f;
    float4 p0 = make_float4(s * w0.x, s * w0.y, s * w0.z, s * w0.w);
    float4 p1 = make_float4(s * w1.x, s * w1.y, s * w1.z, s * w1.w);
    *reinterpret_cast<float4*>(&g_Wps[(size_t)tid * 8]) = p0;
    *reinterpret_cast<float4*>(&g_Wps[(size_t)tid * 8 + 4]) = p1;
    __half h[8];
    h[0] = __float2half_rn(0.1f * p0.x); h[1] = __float2half_rn(0.1f * p0.y);
    h[2] = __float2half_rn(0.1f * p0.z); h[3] = __float2half_rn(0.1f * p0.w);
    h[4] = __float2half_rn(0.1f * p1.x); h[5] = __float2half_rn(0.1f * p1.y);
    h[6] = __float2half_rn(0.1f * p1.z); h[7] = __float2half_rn(0.1f * p1.w);
    *reinterpret_cast<uint4*>(&g_A[(size_t)no * IK + i * 8]) =
        *reinterpret_cast<const uint4*>(h);
}

// ---------------------------------------------------------------------------
// G1: s-GEMM with split-K:  sp[kc][b][no] = sum_{ik in chunk} xh[b][ik]*A[no][ik]
// grid 144 = 4 (b-tiles of 64) x 36 (k-chunks). 256 thr = 8 warps (4x2).
__global__ __launch_bounds__(256) void k_sgemm() {
    __shared__ __half Asm[64][72];
    __shared__ __half Bsm[160][72];
    int t = threadIdx.x;
    int bm = blockIdx.x & 3, kc = blockIdx.x >> 2;
    int b0 = bm * 64, kbase = kc * KCW;
    int warp = t >> 5, lane = t & 31;
    int wm = warp >> 1, wn = warp & 1;
    int gr = lane >> 2, tc = lane & 3;

    float acc[10][4];
#pragma unroll
    for (int f = 0; f < 10; f++)
#pragma unroll
        for (int q = 0; q < 4; q++) acc[f][q] = 0.0f;

    for (int st = 0; st < 4; st++) {
        int ks = kbase + st * 64;
        // load A tile 64x64
#pragma unroll
        for (int j = 0; j < 2; j++) {
            int s = j * 256 + t, r = s >> 3, u = s & 7;
            *reinterpret_cast<uint4*>(&Asm[r][u * 8]) =
                *reinterpret_cast<const uint4*>(&g_xh[(size_t)(b0 + r) * IK + ks + u * 8]);
        }
        // load B tile 160x64
#pragma unroll
        for (int j = 0; j < 5; j++) {
            int s = j * 256 + t, r = s >> 3, u = s & 7;
            *reinterpret_cast<uint4*>(&Bsm[r][u * 8]) =
                *reinterpret_cast<const uint4*>(&g_A[(size_t)r * IK + ks + u * 8]);
        }
        __syncthreads();
#pragma unroll
        for (int kk = 0; kk < 4; kk++) {
            int col = kk * 16;
            uint32_t a0 = ld_h2(&Asm[wm * 16 + gr][col + 2 * tc]);
            uint32_t a1 = ld_h2(&Asm[wm * 16 + gr + 8][col + 2 * tc]);
            uint32_t a2 = ld_h2(&Asm[wm * 16 + gr][col + 2 * tc + 8]);
            uint32_t a3 = ld_h2(&Asm[wm * 16 + gr + 8][col + 2 * tc + 8]);
#pragma unroll
            for (int f = 0; f < 10; f++) {
                int br = wn * 80 + f * 8 + gr;
                uint32_t bb0 = ld_h2(&Bsm[br][col + 2 * tc]);
                uint32_t bb1 = ld_h2(&Bsm[br][col + 2 * tc + 8]);
                mma16816(acc[f], a0, a1, a2, a3, bb0, bb1);
            }
        }
        __syncthreads();
    }
    // write partials
#pragma unroll
    for (int f = 0; f < 10; f++) {
        int no = wn * 80 + f * 8 + 2 * tc;
        int r0 = b0 + wm * 16 + gr;
        *reinterpret_cast<float2*>(&g_sp[kc][(size_t)r0 * NO + no]) =
            make_float2(acc[f][0], acc[f][1]);
        *reinterpret_cast<float2*>(&g_sp[kc][(size_t)(r0 + 8) * NO + no]) =
            make_float2(acc[f][2], acc[f][3]);
    }
}

// ---------------------------------------------------------------------------
// G2: reduce split-K partials + squash -> out (fp32), vT (fp16).
// grid 256 (=b), block 160 (=no).
__global__ __launch_bounds__(160) void k_squash(float* __restrict__ out, int last) {
    int b = blockIdx.x, no = threadIdx.x;
    float s = 0.0f;
#pragma unroll
    for (int kc = 0; kc < KC; kc++) s += g_sp[kc][(size_t)b * NO + no];
    float m = s * s;
    m += __shfl_xor_sync(0xffffffffu, m, 1);
    m += __shfl_xor_sync(0xffffffffu, m, 2);
    m += __shfl_xor_sync(0xffffffffu, m, 4);
    m += __shfl_xor_sync(0xffffffffu, m, 8);
    float v = s * (sqrtf(m) / (1.0f + m));
    out[(size_t)b * NO + no] = v;
    if (!last) g_vT[(size_t)no * BB + b] = __float2half_rn(v);
}

// ---------------------------------------------------------------------------
// G3: fused uv-GEMM + routing update + A-build.
//   C[ik][no] = sum_b xhT[ik][b]*vT[no][b]   (M=64 tile, N=160, K=256)
//   uv[i,n] = (1/B) sum_{k,o} Wps[i,n,o,k]*C[(ik)][(no)]
//   b_ij += uv ; c = softmax_n(b_ij) ; A[no][ik] = c[i,n]*Wps[i,n,o,k]
// grid 144 (i-chunks of 8), 256 thr.
__global__ __launch_bounds__(256) void k_uv(int first) {
    __shared__ __half Asm[64][72];
    __shared__ __half Bsm[160][72];
    __shared__ float suv[8][10];
    __shared__ float cs[8][10];
    int t = threadIdx.x;
    int iblk0 = blockIdx.x * 8;
    int ikbase = blockIdx.x * 64;
    int warp = t >> 5, lane = t & 31;
    int wm = warp >> 1, wn = warp & 1;
    int gr = lane >> 2, tc = lane & 3;

    float acc[10][4];
#pragma unroll
    for (int f = 0; f < 10; f++)
#pragma unroll
        for (int q = 0; q < 4; q++) acc[f][q] = 0.0f;

    for (int st = 0; st < 4; st++) {
        int bs = st * 64;
#pragma unroll
        for (int j = 0; j < 2; j++) {
            int s = j * 256 + t, r = s >> 3, u = s & 7;
            *reinterpret_cast<uint4*>(&Asm[r][u * 8]) =
                *reinterpret_cast<const uint4*>(&g_xhT[(size_t)(ikbase + r) * BB + bs + u * 8]);
        }
#pragma unroll
        for (int j = 0; j < 5; j++) {
            int s = j * 256 + t, r = s >> 3, u = s & 7;
            *reinterpret_cast<uint4*>(&Bsm[r][u * 8]) =
                *reinterpret_cast<const uint4*>(&g_vT[(size_t)r * BB + bs + u * 8]);
        }
        __syncthreads();
#pragma unroll
        for (int kk = 0; kk < 4; kk++) {
            int col = kk * 16;
            uint32_t a0 = ld_h2(&Asm[wm * 16 + gr][col + 2 * tc]);
            uint32_t a1 = ld_h2(&Asm[wm * 16 + gr + 8][col + 2 * tc]);
            uint32_t a2 = ld_h2(&Asm[wm * 16 + gr][col + 2 * tc + 8]);
            uint32_t a3 = ld_h2(&Asm[wm * 16 + gr + 8][col + 2 * tc + 8]);
#pragma unroll
            for (int f = 0; f < 10; f++) {
                int br = wn * 80 + f * 8 + gr;
                uint32_t bb0 = ld_h2(&Bsm[br][col + 2 * tc]);
                uint32_t bb1 = ld_h2(&Bsm[br][col + 2 * tc + 8]);
                mma16816(acc[f], a0, a1, a2, a3, bb0, bb1);
            }
        }
        __syncthreads();
    }

    // epilogue: weight C frags with Wps and reduce over (k,o) -> uv partials
    int i0g = iblk0 + wm * 2;       // rows gr   -> i0g, k = gr
    int i1g = i0g + 1;              // rows gr+8 -> i1g, k = gr
    float p[2][5];
#pragma unroll
    for (int il = 0; il < 2; il++)
#pragma unroll
        for (int nl = 0; nl < 5; nl++) p[il][nl] = 0.0f;

#pragma unroll
    for (int f = 0; f < 10; f++) {
        int no = wn * 80 + f * 8 + 2 * tc;
        int n = no >> 4, o = no & 15;
        float w00 = g_Wps[(((size_t)i0g * NN + n) * OO + o) * KK + gr];
        float w01 = g_Wps[(((size_t)i0g * NN + n) * OO + o + 1) * KK + gr];
        float w10 = g_Wps[(((size_t)i1g * NN + n) * OO + o) * KK + gr];
        float w11 = g_Wps[(((size_t)i1g * NN + n) * OO + o + 1) * KK + gr];
        int nl = f >> 1;
        p[0][nl] += acc[f][0] * w00 + acc[f][1] * w01;
        p[1][nl] += acc[f][2] * w10 + acc[f][3] * w11;
    }
#pragma unroll
    for (int il = 0; il < 2; il++)
#pragma unroll
        for (int nl = 0; nl < 5; nl++) {
            float v = p[il][nl];
#pragma unroll
            for (int off = 16; off > 0; off >>= 1)
                v += __shfl_xor_sync(0xffffffffu, v, off);
            if (lane == 0) suv[wm * 2 + il][wn * 5 + nl] = v;
        }
    __syncthreads();

    if (t < 8) {
        int i = iblk0 + t;
        float bv[NN];
        float mx = -1e30f;
#pragma unroll
        for (int n = 0; n < NN; n++) {
            float bp = first ? 0.0f : g_bij[i * NN + n];
            bv[n] = bp + suv[t][n] * (1.0f / BB);
            g_bij[i * NN + n] = bv[n];
            mx = fmaxf(mx, bv[n]);
        }
        float sum = 0.0f;
#pragma unroll
        for (int n = 0; n < NN; n++) { bv[n] = __expf(bv[n] - mx); sum += bv[n]; }
        float inv = 1.0f / sum;
#pragma unroll
        for (int n = 0; n < NN; n++) cs[t][n] = bv[n] * inv;
    }
    __syncthreads();

    // A-build for this block's i-range: A[no][ikbase..+64) = c[i,n]*Wps
#pragma unroll
    for (int j = 0; j < 20; j++) {
        int s = j * 256 + t;            // 5120 half2 slots
        int no = s >> 5, cp = s & 31;
        int k2 = cp * 2;
        int il = cp >> 2, k = k2 & 7;
        int n = no >> 4, o = no & 15;
        float2 wv = *reinterpret_cast<const float2*>(
            &g_Wps[(((size_t)(iblk0 + il) * NN + n) * OO + o) * KK + k]);
        float cc = cs[il][n];
        __half2 h = __floats2half2_rn(cc * wv.x, cc * wv.y);
        *reinterpret_cast<__half2*>(&g_A[(size_t)no * IK + ikbase + k2]) = h;
    }
}

// ---------------------------------------------------------------------------
extern "C" void kernel_launch(void* const* d_in, const int* in_sizes, int n_in,
                              void* d_out, int out_size) {
    const float* x = (const float*)d_in[0];   // (256, 8, 1152) fp32
    const float* W = (const float*)d_in[1];   // (1, 1152, 10, 16, 8) fp32
    float* out = (float*)d_out;               // (256, 10, 16, 1) fp32

    k_prep_x<<<dim3(II / 32, BB / 32), 256>>>(x);
    k_prep_w<<<(II * NO + 255) / 256, 256>>>(W);

    // iter 1 (c = 0.1 baked into A0)
    k_sgemm<<<4 * KC, 256>>>();
    k_squash<<<BB, NO>>>(out, 0);
    k_uv<<<II / 8, 256>>>(1);
    // iter 2
    k_sgemm<<<4 * KC, 256>>>();
    k_squash<<<BB, NO>>>(out, 0);
    k_uv<<<II / 8, 256>>>(0);
    // iter 3
    k_sgemm<<<4 * KC, 256>>>();
    k_squash<<<BB, NO>>>(out, 1);
}